// round 7
// baseline (speedup 1.0000x reference)
#include <cuda_runtime.h>
#include <cstdint>
#include <math.h>

// Problem dims
#define B_   64
#define T_   512
#define NU_  256
#define NX_  1024

// Recurrence config: 128 blocks = 2 row-groups x 64 col-groups.
// Block owns 32 rows x 16 cols. 256 threads: thread -> (row_l = tid>>3, colpair cp = tid&7).
#define GBLKS    128
#define GPB      64          // blocks per row-group
#define RPB      32          // rows per block
#define CPB      16          // cols per block
#define RTHREADS 256
#define KC       64          // k-chunk size
#define NCHK     16          // chunks per phase
#define NBUF     4
#define XLD      68          // padded chunk row stride (272B, 16B-aligned)
#define BUFF     (RPB * XLD) // 2176 floats per buffer

// Phase-1 GEMM config
#define BM 64
#define BN 64
#define BK 16

typedef unsigned long long u64;

// ---------------- device scratch ----------------
__device__ float d_az[(size_t)B_ * T_ * NX_];
__device__ float d_af[(size_t)B_ * T_ * NX_];
__device__ float d_ar[(size_t)B_ * T_ * NX_];
__device__ float d_xA[B_ * NX_];
__device__ float d_xB[B_ * NX_];
__device__ float d_g[B_ * NX_];
__device__ unsigned d_barc[64];   // [rg*32]: two counters 128B apart

// ---------------- packed f32x2 helpers (sm_103a) ----------------
__device__ __forceinline__ u64 pack2(float x, float y) {
    u64 r; asm("mov.b64 %0, {%1,%2};" : "=l"(r) : "f"(x), "f"(y)); return r;
}
__device__ __forceinline__ void ffma2(u64& d, u64 a, u64 b) {
    asm("fma.rn.f32x2 %0, %1, %2, %0;" : "+l"(d) : "l"(a), "l"(b));
}
__device__ __forceinline__ void unpack2(u64 v, float& x, float& y) {
    asm("mov.b64 {%0,%1}, %2;" : "=f"(x), "=f"(y) : "l"(v));
}

// ---------------- cp.async helpers ----------------
__device__ __forceinline__ void cp_async16(void* smem_dst, const void* gmem_src) {
    uint32_t saddr = (uint32_t)__cvta_generic_to_shared(smem_dst);
    asm volatile("cp.async.cg.shared.global [%0], [%1], 16;\n" :: "r"(saddr), "l"(gmem_src));
}
__device__ __forceinline__ void cp_commit() { asm volatile("cp.async.commit_group;\n"); }
template <int N>
__device__ __forceinline__ void cp_wait() { asm volatile("cp.async.wait_group %0;\n" :: "n"(N)); }

// Load chunk c of src (RPB rows, row stride NX_) into a ring buffer. One commit group.
// 32 rows x 64 floats = 512 float4; 2 per thread.
__device__ __forceinline__ void load_chunk(float* dst, const float* src, int c, int tid) {
    const int cb = c * KC;
#pragma unroll
    for (int q = 0; q < 2; ++q) {
        const int idx = tid + q * RTHREADS;   // 0..511
        const int row = idx >> 4;             // 16 float4 per row
        const int c4  = idx & 15;
        cp_async16(dst + row * XLD + c4 * 4, src + (size_t)row * NX_ + cb + c4 * 4);
    }
    cp_commit();
}

// ---------------- per-row-group monotone barrier (64 blocks) ----------------
__device__ __forceinline__ void group_barrier(unsigned* ctr, unsigned target) {
    __syncthreads();
    if (threadIdx.x == 0) {
        unsigned old;
        asm volatile("atom.add.release.gpu.global.u32 %0, [%1], 1;"
                     : "=r"(old) : "l"(ctr) : "memory");
        unsigned cur;
        int spins = 0;
        do {
            asm volatile("ld.acquire.gpu.global.u32 %0, [%1];"
                         : "=r"(cur) : "l"(ctr) : "memory");
            if (cur >= target) break;
            if (++spins > 4) __nanosleep(40);
        } while (true);
    }
    __syncthreads();
}

// ---------------- init ----------------
__global__ void init_kernel(const float* __restrict__ x0) {
    if (blockIdx.x == 0 && threadIdx.x < 2) d_barc[threadIdx.x * 32] = 0;
    const int i = blockIdx.x * blockDim.x + threadIdx.x;
    float4 v = *(const float4*)&x0[i * 4];
    *(float4*)&d_xA[i * 4] = v;
}

// ---------------- Phase 1: a{z,f,r} = u @ W + b (FFMA2) ----------------
__global__ void __launch_bounds__(256) inproj_kernel(
    const float* __restrict__ u,
    const float* __restrict__ Wz, const float* __restrict__ Wf, const float* __restrict__ Wr,
    const float* __restrict__ bz, const float* __restrict__ bf, const float* __restrict__ br)
{
    __shared__ float As[BM][BK + 1];
    __shared__ float Bs[BK][BN];

    const int gate = blockIdx.z;
    const float* W    = (gate == 0) ? Wz : (gate == 1) ? Wf : Wr;
    const float* bias = (gate == 0) ? bz : (gate == 1) ? bf : br;
    float* out        = (gate == 0) ? d_az : (gate == 1) ? d_af : d_ar;

    const int m0 = blockIdx.y * BM;
    const int n0 = blockIdx.x * BN;
    const int tid = threadIdx.x;
    const int tx = tid % 16;
    const int ty = tid / 16;

    u64 acc01[4], acc23[4];
#pragma unroll
    for (int i = 0; i < 4; i++) { acc01[i] = 0; acc23[i] = 0; }

    for (int k0 = 0; k0 < NU_; k0 += BK) {
        {
            const int r = tid >> 2, q = tid & 3;
            float4 v = *(const float4*)&u[(size_t)(m0 + r) * NU_ + k0 + q * 4];
            As[r][q * 4 + 0] = v.x; As[r][q * 4 + 1] = v.y;
            As[r][q * 4 + 2] = v.z; As[r][q * 4 + 3] = v.w;
        }
        {
            const int r = tid >> 4, q = tid & 15;
            float4 v = *(const float4*)&W[(size_t)(k0 + r) * NX_ + n0 + q * 4];
            *(float4*)&Bs[r][q * 4] = v;
        }
        __syncthreads();
#pragma unroll
        for (int kk = 0; kk < BK; ++kk) {
            const u64 b01 = *(const u64*)&Bs[kk][tx * 4];
            const u64 b23 = *(const u64*)&Bs[kk][tx * 4 + 2];
#pragma unroll
            for (int i = 0; i < 4; i++) {
                const float av = As[ty * 4 + i][kk];
                const u64 pa = pack2(av, av);
                ffma2(acc01[i], pa, b01);
                ffma2(acc23[i], pa, b23);
            }
        }
        __syncthreads();
    }

    const float b0 = __ldg(&bias[n0 + tx * 4 + 0]);
    const float b1 = __ldg(&bias[n0 + tx * 4 + 1]);
    const float b2 = __ldg(&bias[n0 + tx * 4 + 2]);
    const float b3 = __ldg(&bias[n0 + tx * 4 + 3]);
#pragma unroll
    for (int i = 0; i < 4; i++) {
        float v0, v1, v2, v3;
        unpack2(acc01[i], v0, v1);
        unpack2(acc23[i], v2, v3);
        float4 o = make_float4(v0 + b0, v1 + b1, v2 + b2, v3 + b3);
        *(float4*)&out[(size_t)(m0 + ty * 4 + i) * NX_ + n0 + tx * 4] = o;
    }
}

// ---------------- Phase 2: persistent recurrence (2D-tiled, group barriers) ----------------
extern __shared__ float recur_smem[];

__global__ void __launch_bounds__(RTHREADS, 1) recur_kernel(
    const float* __restrict__ Uz, const float* __restrict__ Uf, const float* __restrict__ Ur,
    float* __restrict__ out)
{
    float* Uzf  = recur_smem;                  // [1024][16 cols][2 gates] = 32768 f (128KB)
    float* Urs  = Uzf + NX_ * 2 * CPB;         // [1024][16] = 16384 f (64KB)
    float* bufs = Urs + NX_ * CPB;             // 4 * 2176 f (34KB)

    const int tid = threadIdx.x;
    const int bid = blockIdx.x;
    const int rg  = bid >> 6;                  // row-group 0/1
    const int cg  = bid & 63;                  // col-group
    const int j0  = cg * CPB;
    const int row_l = tid >> 3;                // 0..31
    const int cp    = tid & 7;                 // 0..7 (2 cols each)
    const int row   = rg * RPB + row_l;
    const int jc    = j0 + cp * 2;

    // Stage U slices (one-time). Uzf interleaved {Uz, Uf} per column.
    for (int i = tid; i < NX_ * CPB; i += RTHREADS) {
        const int k = i >> 4, col = i & 15;
        Uzf[k * 32 + col * 2 + 0] = __ldg(&Uz[(size_t)k * NX_ + j0 + col]);
        Uzf[k * 32 + col * 2 + 1] = __ldg(&Uf[(size_t)k * NX_ + j0 + col]);
        Urs[k * 16 + col]         = __ldg(&Ur[(size_t)k * NX_ + j0 + col]);
    }
    __syncthreads();

    // Per-thread U views. Per k: Uzf row = 8 ulonglong2 (this thread takes #cp:
    // {col 2cp:{z,f}, col 2cp+1:{z,f}}); Urs row = 8 u64 (#cp = cols {2cp, 2cp+1}).
    const ulonglong2* Uzf2 = (const ulonglong2*)Uzf + cp;
    const u64*        Ur1  = (const u64*)Urs + cp;

    float* xcur  = d_xA;
    float* xnext = d_xB;
    unsigned* ctr = &d_barc[rg * 32];
    unsigned target = GPB;

    for (int t = 0; t < T_; ++t) {
        const size_t aoff = ((size_t)row * T_ + t) * NX_ + jc;

        // ================= ZF phase: z = sig(az + x@Uz), f = sig(af + x@Uf) ============
        u64 accA = 0, accB = 0;   // accA = {z,f} col jc; accB = {z,f} col jc+1
        const float2 az2 = __ldcs((const float2*)&d_az[aoff]);
        const float2 af2 = __ldcs((const float2*)&d_af[aoff]);

        const float* xsrc = xcur + (size_t)rg * RPB * NX_;
        load_chunk(bufs + 0 * BUFF, xsrc, 0, tid);
        load_chunk(bufs + 1 * BUFF, xsrc, 1, tid);
        load_chunk(bufs + 2 * BUFF, xsrc, 2, tid);
#pragma unroll 1
        for (int p = 0; p < NCHK; ++p) {
            if (p < NCHK - 2) cp_wait<2>(); else if (p == NCHK - 2) cp_wait<1>(); else cp_wait<0>();
            __syncthreads();
            if (p + 3 < NCHK) load_chunk(bufs + ((p + 3) & 3) * BUFF, xsrc, p + 3, tid);
            const float* xb = bufs + (p & 3) * BUFF + row_l * XLD;
            const int kbase = p * KC;
#pragma unroll 8
            for (int kk2 = 0; kk2 < KC / 2; ++kk2) {
                const float2 xp = *(const float2*)(xb + kk2 * 2);
                const u64 px0 = pack2(xp.x, xp.x);
                const u64 px1 = pack2(xp.y, xp.y);
                const int k = kbase + kk2 * 2;
                const ulonglong2 Ua = Uzf2[(size_t)k * 8];
                const ulonglong2 Ub = Uzf2[(size_t)(k + 1) * 8];
                ffma2(accA, px0, Ua.x); ffma2(accB, px0, Ua.y);
                ffma2(accA, px1, Ub.x); ffma2(accB, px1, Ub.y);
            }
        }
        float zr0, fr0, zr1, fr1;
        unpack2(accA, zr0, fr0);
        unpack2(accB, zr1, fr1);
        zr0 += az2.x; zr1 += az2.y; fr0 += af2.x; fr1 += af2.y;
        const float z0 = 1.0f / (1.0f + __expf(-zr0));
        const float z1 = 1.0f / (1.0f + __expf(-zr1));
        const float f0 = 1.0f / (1.0f + __expf(-fr0));
        const float f1 = 1.0f / (1.0f + __expf(-fr1));

        const float2 xc2 = __ldcg((const float2*)&xcur[(size_t)row * NX_ + jc]);
        // io_delay: output at step t is the PRE-update state
        __stcs((float2*)&out[aoff], xc2);
        __stcg((float2*)&d_g[(size_t)row * NX_ + jc], make_float2(f0 * xc2.x, f1 * xc2.y));

        group_barrier(ctr, target); target += GPB;   // g rows of this group visible

        // ================= R phase: r = tanh(ar + g@Ur); x_next = z*x + (1-z)*r ========
        u64 accR = 0;   // {r col jc, r col jc+1}
        const float2 ar2 = __ldcs((const float2*)&d_ar[aoff]);

        const float* gsrc = d_g + (size_t)rg * RPB * NX_;
        load_chunk(bufs + 0 * BUFF, gsrc, 0, tid);
        load_chunk(bufs + 1 * BUFF, gsrc, 1, tid);
        load_chunk(bufs + 2 * BUFF, gsrc, 2, tid);
#pragma unroll 1
        for (int p = 0; p < NCHK; ++p) {
            if (p < NCHK - 2) cp_wait<2>(); else if (p == NCHK - 2) cp_wait<1>(); else cp_wait<0>();
            __syncthreads();
            if (p + 3 < NCHK) load_chunk(bufs + ((p + 3) & 3) * BUFF, gsrc, p + 3, tid);
            const float* gb = bufs + (p & 3) * BUFF + row_l * XLD;
            const int kbase = p * KC;
#pragma unroll 8
            for (int kk2 = 0; kk2 < KC / 2; ++kk2) {
                const float2 gp = *(const float2*)(gb + kk2 * 2);
                const u64 pg0 = pack2(gp.x, gp.x);
                const u64 pg1 = pack2(gp.y, gp.y);
                const int k = kbase + kk2 * 2;
                const u64 Ua = Ur1[(size_t)k * 8];
                const u64 Ub = Ur1[(size_t)(k + 1) * 8];
                ffma2(accR, pg0, Ua);
                ffma2(accR, pg1, Ub);
            }
        }
        float rr0, rr1;
        unpack2(accR, rr0, rr1);
        rr0 += ar2.x; rr1 += ar2.y;
        float2 xn;
        xn.x = z0 * xc2.x + (1.0f - z0) * tanhf(rr0);
        xn.y = z1 * xc2.y + (1.0f - z1) * tanhf(rr1);
        __stcg((float2*)&xnext[(size_t)row * NX_ + jc], xn);

        group_barrier(ctr, target); target += GPB;   // x_next rows of this group written

        float* tmp = xcur; xcur = xnext; xnext = tmp;
    }
}

// ---------------- launch ----------------
extern "C" void kernel_launch(void* const* d_in, const int* in_sizes, int n_in,
                              void* d_out, int out_size) {
    const float* u  = (const float*)d_in[0];
    const float* x0 = (const float*)d_in[1];
    const float* Wz = (const float*)d_in[2];
    const float* Uz = (const float*)d_in[3];
    const float* bz = (const float*)d_in[4];
    const float* Wf = (const float*)d_in[5];
    const float* Uf = (const float*)d_in[6];
    const float* bf = (const float*)d_in[7];
    const float* Wr = (const float*)d_in[8];
    const float* Ur = (const float*)d_in[9];
    const float* br = (const float*)d_in[10];
    float* out = (float*)d_out;

    init_kernel<<<64, 256>>>(x0);

    dim3 g1(NX_ / BN, (B_ * T_) / BM, 3);
    inproj_kernel<<<g1, 256>>>(u, Wz, Wf, Wr, bz, bf, br);

    // smem: Uzf 131072B + Ur 65536B + 4*8704B bufs = 231,424 B (<= 227KB limit)
    const int smem_bytes = (NX_ * 2 * CPB + NX_ * CPB + NBUF * BUFF) * (int)sizeof(float);
    cudaFuncSetAttribute(recur_kernel, cudaFuncAttributeMaxDynamicSharedMemorySize, smem_bytes);
    recur_kernel<<<GBLKS, RTHREADS, smem_bytes>>>(Uz, Uf, Ur, out);
}

// round 9
// speedup vs baseline: 1.3153x; 1.3153x over previous
#include <cuda_runtime.h>
#include <cstdint>
#include <math.h>

// Problem dims
#define B_   64
#define T_   512
#define NU_  256
#define NX_  1024

// Recurrence config: 128 blocks, block owns all 64 rows x 8 cols.
// 512 threads = 4 K-groups x 128 slots. Slot s: row = s>>1, ui = s&1 (4 cols).
#define GBLKS    128
#define CPB      8
#define RTHREADS 512
#define KC       64
#define NBUF     6
#define XLD      68          // padded chunk row stride (272B, 16B-aligned)
#define BUFF     (B_ * XLD)  // 4352 floats per buffer

// Phase-1 GEMM config
#define BM 64
#define BN 64
#define BK 16

typedef unsigned long long u64;

// ---------------- device scratch ----------------
__device__ float d_az[(size_t)B_ * T_ * NX_];
__device__ float d_af[(size_t)B_ * T_ * NX_];
__device__ float d_ar[(size_t)B_ * T_ * NX_];
__device__ float d_xA[B_ * NX_];
__device__ float d_xB[B_ * NX_];
__device__ float d_g[B_ * NX_];
__device__ unsigned d_barcount;

// ---------------- packed f32x2 helpers (sm_103a) ----------------
__device__ __forceinline__ u64 pack2(float x, float y) {
    u64 r; asm("mov.b64 %0, {%1,%2};" : "=l"(r) : "f"(x), "f"(y)); return r;
}
__device__ __forceinline__ void ffma2(u64& d, u64 a, u64 b) {
    asm("fma.rn.f32x2 %0, %1, %2, %0;" : "+l"(d) : "l"(a), "l"(b));
}
__device__ __forceinline__ u64 fadd2(u64 a, u64 b) {
    u64 r; asm("add.rn.f32x2 %0, %1, %2;" : "=l"(r) : "l"(a), "l"(b)); return r;
}
__device__ __forceinline__ void unpack2(u64 v, float& x, float& y) {
    asm("mov.b64 {%0,%1}, %2;" : "=f"(x), "=f"(y) : "l"(v));
}

// ---------------- cp.async helpers ----------------
__device__ __forceinline__ void cp_async16(void* smem_dst, const void* gmem_src) {
    uint32_t saddr = (uint32_t)__cvta_generic_to_shared(smem_dst);
    asm volatile("cp.async.cg.shared.global [%0], [%1], 16;\n" :: "r"(saddr), "l"(gmem_src));
}
__device__ __forceinline__ void cp_commit() { asm volatile("cp.async.commit_group;\n"); }
template <int N>
__device__ __forceinline__ void cp_wait() { asm volatile("cp.async.wait_group %0;\n" :: "n"(N)); }

// Load chunk pair (2*pair, 2*pair+1) of src [64][NX_] into ring buffers. One commit group.
// Per chunk: 64 rows x 16 float4 = 1024 transfers; 2 per thread at 512 threads.
__device__ __forceinline__ void load_pair(float* bufs, const float* src, int pair, int tid) {
#pragma unroll
    for (int h = 0; h < 2; ++h) {
        const int c = 2 * pair + h;
        float* dst = bufs + (c % NBUF) * BUFF;
        const int cb = c * KC;
#pragma unroll
        for (int q = 0; q < 2; ++q) {
            const int idx = tid + q * RTHREADS;   // 0..1023
            const int row = idx >> 4;
            const int c4  = idx & 15;
            cp_async16(dst + row * XLD + c4 * 4, src + (size_t)row * NX_ + cb + c4 * 4);
        }
    }
    cp_commit();
}

// ---------------- grid-wide monotone barrier ----------------
__device__ __forceinline__ void grid_barrier(unsigned target) {
    __syncthreads();
    if (threadIdx.x == 0) {
        unsigned old;
        asm volatile("atom.add.release.gpu.global.u32 %0, [%1], 1;"
                     : "=r"(old) : "l"(&d_barcount) : "memory");
        unsigned cur;
        int spins = 0;
        do {
            asm volatile("ld.acquire.gpu.global.u32 %0, [%1];"
                         : "=r"(cur) : "l"(&d_barcount) : "memory");
            if (cur >= target) break;
            if (++spins > 4) __nanosleep(40);
        } while (true);
    }
    __syncthreads();
}

// ---------------- init ----------------
__global__ void init_kernel(const float* __restrict__ x0) {
    if (blockIdx.x == 0 && threadIdx.x == 0) d_barcount = 0;
    const int i = blockIdx.x * blockDim.x + threadIdx.x;
    float4 v = *(const float4*)&x0[i * 4];
    *(float4*)&d_xA[i * 4] = v;
}

// ---------------- Phase 1: a{z,f,r} = u @ W + b (FFMA2) ----------------
__global__ void __launch_bounds__(256) inproj_kernel(
    const float* __restrict__ u,
    const float* __restrict__ Wz, const float* __restrict__ Wf, const float* __restrict__ Wr,
    const float* __restrict__ bz, const float* __restrict__ bf, const float* __restrict__ br)
{
    __shared__ float As[BM][BK + 1];
    __shared__ float Bs[BK][BN];

    const int gate = blockIdx.z;
    const float* W    = (gate == 0) ? Wz : (gate == 1) ? Wf : Wr;
    const float* bias = (gate == 0) ? bz : (gate == 1) ? bf : br;
    float* out        = (gate == 0) ? d_az : (gate == 1) ? d_af : d_ar;

    const int m0 = blockIdx.y * BM;
    const int n0 = blockIdx.x * BN;
    const int tid = threadIdx.x;
    const int tx = tid % 16;
    const int ty = tid / 16;

    u64 acc01[4], acc23[4];
#pragma unroll
    for (int i = 0; i < 4; i++) { acc01[i] = 0; acc23[i] = 0; }

    for (int k0 = 0; k0 < NU_; k0 += BK) {
        {
            const int r = tid >> 2, q = tid & 3;
            float4 v = *(const float4*)&u[(size_t)(m0 + r) * NU_ + k0 + q * 4];
            As[r][q * 4 + 0] = v.x; As[r][q * 4 + 1] = v.y;
            As[r][q * 4 + 2] = v.z; As[r][q * 4 + 3] = v.w;
        }
        {
            const int r = tid >> 4, q = tid & 15;
            float4 v = *(const float4*)&W[(size_t)(k0 + r) * NX_ + n0 + q * 4];
            *(float4*)&Bs[r][q * 4] = v;
        }
        __syncthreads();
#pragma unroll
        for (int kk = 0; kk < BK; ++kk) {
            const u64 b01 = *(const u64*)&Bs[kk][tx * 4];
            const u64 b23 = *(const u64*)&Bs[kk][tx * 4 + 2];
#pragma unroll
            for (int i = 0; i < 4; i++) {
                const float av = As[ty * 4 + i][kk];
                const u64 pa = pack2(av, av);
                ffma2(acc01[i], pa, b01);
                ffma2(acc23[i], pa, b23);
            }
        }
        __syncthreads();
    }

    const float b0 = __ldg(&bias[n0 + tx * 4 + 0]);
    const float b1 = __ldg(&bias[n0 + tx * 4 + 1]);
    const float b2 = __ldg(&bias[n0 + tx * 4 + 2]);
    const float b3 = __ldg(&bias[n0 + tx * 4 + 3]);
#pragma unroll
    for (int i = 0; i < 4; i++) {
        float v0, v1, v2, v3;
        unpack2(acc01[i], v0, v1);
        unpack2(acc23[i], v2, v3);
        float4 o = make_float4(v0 + b0, v1 + b1, v2 + b2, v3 + b3);
        *(float4*)&out[(size_t)(m0 + ty * 4 + i) * NX_ + n0 + tx * 4] = o;
    }
}

// ---------------- Phase 2: persistent recurrence (4-way split-K, 512 threads) ----------------
// Group q = tid>>7 handles chunks c with c%4 == q. Slot s = tid&127: row = s>>1, ui = s&1.
// ZF dual-gate: acc = {z,f} per column via fma.rn.f32x2, Uz/Uf interleaved in smem.
extern __shared__ float recur_smem[];

__global__ void __launch_bounds__(RTHREADS, 1) recur_kernel(
    const float* __restrict__ Uz, const float* __restrict__ Uf, const float* __restrict__ Ur,
    float* __restrict__ out)
{
    float* Uzf  = recur_smem;                  // [NX_][8 cols][2 gates] = 16384 f
    float* Urs  = Uzf + NX_ * 16;              // [NX_][8] = 8192 f
    float* bufs = Urs + NX_ * 8;               // 6 * 4352 f
    u64*   scr  = (u64*)(bufs + NBUF * BUFF);  // 1536 u64 reduction scratch

    const int tid = threadIdx.x;
    const int bid = blockIdx.x;
    const int j0 = bid * CPB;

    const int s   = tid & 127;
    const int q   = tid >> 7;                  // K-group 0..3
    const int row = s >> 1;
    const int ui  = s & 1;
    const int jb  = j0 + ui * 4;

    // Stage U slices (one-time). Uzf interleaved {Uz, Uf} per column.
    for (int i = tid; i < NX_ * 8; i += RTHREADS) {
        const int k = i >> 3, col = i & 7;
        Uzf[k * 16 + col * 2 + 0] = __ldg(&Uz[(size_t)k * NX_ + j0 + col]);
        Uzf[k * 16 + col * 2 + 1] = __ldg(&Uf[(size_t)k * NX_ + j0 + col]);
        Urs[i]                    = __ldg(&Ur[(size_t)k * NX_ + j0 + col]);
    }
    __syncthreads();

    const ulonglong2* UzfT = (const ulonglong2*)Uzf + ui * 2;   // + k*4 per k
    const ulonglong2* UrT  = (const ulonglong2*)Urs + ui;       // + k*2 per k

    float* xcur  = d_xA;
    float* xnext = d_xB;
    unsigned target = GBLKS;

    float zv[4];     // z gate values (group 0 threads)
    float4 xc;       // current state for this thread's 4 cols

    for (int t = 0; t < T_; ++t) {
        // ================= ZF phase =================
        u64 acc0 = 0, acc1 = 0, acc2 = 0, acc3 = 0;
        float4 az4, af4;
        if (q == 0) {
            az4 = __ldcs((const float4*)&d_az[((size_t)row * T_ + t) * NX_ + jb]);
            af4 = __ldcs((const float4*)&d_af[((size_t)row * T_ + t) * NX_ + jb]);
        }

        load_pair(bufs, xcur, 0, tid);
        load_pair(bufs, xcur, 1, tid);
        load_pair(bufs, xcur, 2, tid);
#pragma unroll 1
        for (int p = 0; p < 4; ++p) {
            if (p < 3) cp_wait<1>(); else cp_wait<0>();
            __syncthreads();
            const int c = 4 * p + q;
            const float* xb = bufs + (c % NBUF) * BUFF + row * XLD;
            const int k0 = c * KC;
#pragma unroll 8
            for (int kk2 = 0; kk2 < KC / 2; ++kk2) {
                const float2 xp = *(const float2*)(xb + kk2 * 2);
                const u64 p0 = pack2(xp.x, xp.x);
                const u64 p1 = pack2(xp.y, xp.y);
                const int k = k0 + kk2 * 2;
                ulonglong2 A0 = UzfT[(size_t)k * 4];
                ulonglong2 B0 = UzfT[(size_t)k * 4 + 1];
                ffma2(acc0, p0, A0.x); ffma2(acc1, p0, A0.y);
                ffma2(acc2, p0, B0.x); ffma2(acc3, p0, B0.y);
                ulonglong2 A1 = UzfT[(size_t)(k + 1) * 4];
                ulonglong2 B1 = UzfT[(size_t)(k + 1) * 4 + 1];
                ffma2(acc0, p1, A1.x); ffma2(acc1, p1, A1.y);
                ffma2(acc2, p1, B1.x); ffma2(acc3, p1, B1.y);
            }
            __syncthreads();
            if (p == 0)      { load_pair(bufs, xcur, 3, tid); load_pair(bufs, xcur, 4, tid); }
            else if (p == 1) { load_pair(bufs, xcur, 5, tid); load_pair(bufs, xcur, 6, tid); }
            else if (p == 2) { load_pair(bufs, xcur, 7, tid); }
        }
        // cross-group reduction
        if (q > 0) {
            ulonglong2* dst = (ulonglong2*)&scr[(q - 1) * 512 + s * 4];
            dst[0] = make_ulonglong2(acc0, acc1);
            dst[1] = make_ulonglong2(acc2, acc3);
        }
        __syncthreads();
        if (q == 0) {
#pragma unroll
            for (int g = 0; g < 3; ++g) {
                const ulonglong2* src = (const ulonglong2*)&scr[g * 512 + s * 4];
                ulonglong2 o0 = src[0], o1 = src[1];
                acc0 = fadd2(acc0, o0.x); acc1 = fadd2(acc1, o0.y);
                acc2 = fadd2(acc2, o1.x); acc3 = fadd2(acc3, o1.y);
            }
            float zp[4], fp[4];
            unpack2(acc0, zp[0], fp[0]); unpack2(acc1, zp[1], fp[1]);
            unpack2(acc2, zp[2], fp[2]); unpack2(acc3, zp[3], fp[3]);
            zp[0] += az4.x; zp[1] += az4.y; zp[2] += az4.z; zp[3] += az4.w;
            fp[0] += af4.x; fp[1] += af4.y; fp[2] += af4.z; fp[3] += af4.w;
            float fv[4];
#pragma unroll
            for (int c2 = 0; c2 < 4; ++c2) {
                zv[c2] = 1.0f / (1.0f + __expf(-zp[c2]));
                fv[c2] = 1.0f / (1.0f + __expf(-fp[c2]));
            }
            xc = __ldcg((const float4*)&xcur[(size_t)row * NX_ + jb]);
            // io_delay: output at step t is the PRE-update state
            __stcs((float4*)&out[((size_t)row * T_ + t) * NX_ + jb], xc);
            float4 g4;
            g4.x = fv[0] * xc.x; g4.y = fv[1] * xc.y;
            g4.z = fv[2] * xc.z; g4.w = fv[3] * xc.w;
            __stcg((float4*)&d_g[(size_t)row * NX_ + jb], g4);
        }
        grid_barrier(target); target += GBLKS;

        // ================= R phase =================
        u64 racc0 = 0, racc1 = 0;
        float4 ar4;
        if (q == 0)
            ar4 = __ldcs((const float4*)&d_ar[((size_t)row * T_ + t) * NX_ + jb]);

        load_pair(bufs, d_g, 0, tid);
        load_pair(bufs, d_g, 1, tid);
        load_pair(bufs, d_g, 2, tid);
#pragma unroll 1
        for (int p = 0; p < 4; ++p) {
            if (p < 3) cp_wait<1>(); else cp_wait<0>();
            __syncthreads();
            const int c = 4 * p + q;
            const float* gb = bufs + (c % NBUF) * BUFF + row * XLD;
            const int k0 = c * KC;
#pragma unroll 8
            for (int kk2 = 0; kk2 < KC / 2; ++kk2) {
                const float2 gp = *(const float2*)(gb + kk2 * 2);
                const u64 p0 = pack2(gp.x, gp.x);
                const u64 p1 = pack2(gp.y, gp.y);
                const int k = k0 + kk2 * 2;
                ulonglong2 U0 = UrT[(size_t)k * 2];
                ffma2(racc0, p0, U0.x); ffma2(racc1, p0, U0.y);
                ulonglong2 U1 = UrT[(size_t)(k + 1) * 2];
                ffma2(racc0, p1, U1.x); ffma2(racc1, p1, U1.y);
            }
            __syncthreads();
            if (p == 0)      { load_pair(bufs, d_g, 3, tid); load_pair(bufs, d_g, 4, tid); }
            else if (p == 1) { load_pair(bufs, d_g, 5, tid); load_pair(bufs, d_g, 6, tid); }
            else if (p == 2) { load_pair(bufs, d_g, 7, tid); }
        }
        if (q > 0)
            ((ulonglong2*)&scr[0])[(q - 1) * 128 + s] = make_ulonglong2(racc0, racc1);
        __syncthreads();
        if (q == 0) {
#pragma unroll
            for (int g = 0; g < 3; ++g) {
                ulonglong2 o = ((const ulonglong2*)&scr[0])[g * 128 + s];
                racc0 = fadd2(racc0, o.x); racc1 = fadd2(racc1, o.y);
            }
            float rp[4];
            unpack2(racc0, rp[0], rp[1]); unpack2(racc1, rp[2], rp[3]);
            rp[0] += ar4.x; rp[1] += ar4.y; rp[2] += ar4.z; rp[3] += ar4.w;
            float4 xn;
            xn.x = zv[0] * xc.x + (1.0f - zv[0]) * tanhf(rp[0]);
            xn.y = zv[1] * xc.y + (1.0f - zv[1]) * tanhf(rp[1]);
            xn.z = zv[2] * xc.z + (1.0f - zv[2]) * tanhf(rp[2]);
            xn.w = zv[3] * xc.w + (1.0f - zv[3]) * tanhf(rp[3]);
            __stcg((float4*)&xnext[(size_t)row * NX_ + jb], xn);
        }
        grid_barrier(target); target += GBLKS;

        float* tmp = xcur; xcur = xnext; xnext = tmp;
    }
}

// ---------------- launch ----------------
extern "C" void kernel_launch(void* const* d_in, const int* in_sizes, int n_in,
                              void* d_out, int out_size) {
    const float* u  = (const float*)d_in[0];
    const float* x0 = (const float*)d_in[1];
    const float* Wz = (const float*)d_in[2];
    const float* Uz = (const float*)d_in[3];
    const float* bz = (const float*)d_in[4];
    const float* Wf = (const float*)d_in[5];
    const float* Uf = (const float*)d_in[6];
    const float* bf = (const float*)d_in[7];
    const float* Wr = (const float*)d_in[8];
    const float* Ur = (const float*)d_in[9];
    const float* br = (const float*)d_in[10];
    float* out = (float*)d_out;

    init_kernel<<<64, 256>>>(x0);

    dim3 g1(NX_ / BN, (B_ * T_) / BM, 3);
    inproj_kernel<<<g1, 256>>>(u, Wz, Wf, Wr, bz, bf, br);

    // smem: Uzf 16384 + Ur 8192 + bufs 26112 + scr 3072 floats = 215,040 B
    const int smem_bytes = (NX_ * 16 + NX_ * 8 + NBUF * BUFF + 3072) * (int)sizeof(float);
    cudaFuncSetAttribute(recur_kernel, cudaFuncAttributeMaxDynamicSharedMemorySize, smem_bytes);
    recur_kernel<<<GBLKS, RTHREADS, smem_bytes>>>(Uz, Uf, Ur, out);
}

// round 10
// speedup vs baseline: 1.3508x; 1.0270x over previous
#include <cuda_runtime.h>
#include <cstdint>
#include <math.h>

// Problem dims
#define B_   64
#define T_   512
#define NU_  256
#define NX_  1024

// Recurrence config: 128 blocks, block owns all 64 rows x 8 cols.
// 256 threads = 2 K-groups (khalf) x 128 slots. Slot s: row = s>>1, ui = s&1 (4 cols).
#define GBLKS    128
#define CPB      8
#define RTHREADS 256
#define KC       64
#define NBUF     6
#define XLD      68          // padded chunk row stride (272B, 16B-aligned)
#define BUFF     (B_ * XLD)  // 4352 floats per buffer

// Phase-1 GEMM config
#define BM 64
#define BN 64
#define BK 16

typedef unsigned long long u64;

// ---------------- device scratch ----------------
__device__ float d_az[(size_t)B_ * T_ * NX_];
__device__ float d_af[(size_t)B_ * T_ * NX_];
__device__ float d_ar[(size_t)B_ * T_ * NX_];
__device__ float d_xA[B_ * NX_];
__device__ float d_xB[B_ * NX_];
__device__ float d_gA[B_ * NX_];
__device__ float d_gB[B_ * NX_];
// Dataflow flags: one per pair-group (128 cols = 16 producer blocks), padded 128B apart.
__device__ unsigned d_xf[8 * 32];
__device__ unsigned d_gf[8 * 32];

// ---------------- packed f32x2 helpers (sm_103a) ----------------
__device__ __forceinline__ u64 pack2(float x, float y) {
    u64 r; asm("mov.b64 %0, {%1,%2};" : "=l"(r) : "f"(x), "f"(y)); return r;
}
__device__ __forceinline__ void ffma2(u64& d, u64 a, u64 b) {
    asm("fma.rn.f32x2 %0, %1, %2, %0;" : "+l"(d) : "l"(a), "l"(b));
}
__device__ __forceinline__ u64 fadd2(u64 a, u64 b) {
    u64 r; asm("add.rn.f32x2 %0, %1, %2;" : "=l"(r) : "l"(a), "l"(b)); return r;
}
__device__ __forceinline__ void unpack2(u64 v, float& x, float& y) {
    asm("mov.b64 {%0,%1}, %2;" : "=f"(x), "=f"(y) : "l"(v));
}

// ---------------- cp.async helpers ----------------
__device__ __forceinline__ void cp_async16(void* smem_dst, const void* gmem_src) {
    uint32_t saddr = (uint32_t)__cvta_generic_to_shared(smem_dst);
    asm volatile("cp.async.cg.shared.global [%0], [%1], 16;\n" :: "r"(saddr), "l"(gmem_src));
}
__device__ __forceinline__ void cp_commit() { asm volatile("cp.async.commit_group;\n"); }
template <int N>
__device__ __forceinline__ void cp_wait() { asm volatile("cp.async.wait_group %0;\n" :: "n"(N)); }

// Load PAIR `pair` (chunks 2*pair, 2*pair+1) into ring slots for pipeline position `pos`.
// Slot = (2*pos + h) % NBUF, so slots are consumed/refilled in pipeline order even
// though `pair` visits chunk indices in rotated order.
__device__ __forceinline__ void load_pos(float* bufs, const float* src, int pos, int pair, int tid) {
#pragma unroll
    for (int h = 0; h < 2; ++h) {
        float* dst = bufs + ((2 * pos + h) % NBUF) * BUFF;
        const int cb = (2 * pair + h) * KC;
#pragma unroll
        for (int q = 0; q < 4; ++q) {
            const int idx = tid + q * RTHREADS;   // 0..1023
            const int row = idx >> 4;             // 16 float4 per row
            const int c4  = idx & 15;
            cp_async16(dst + row * XLD + c4 * 4, src + (size_t)row * NX_ + cb + c4 * 4);
        }
    }
    cp_commit();
}

// ---------------- dataflow flags ----------------
__device__ __forceinline__ void wait_flag(const unsigned* f, unsigned target) {
    unsigned cur; int spins = 0;
    while (true) {
        asm volatile("ld.acquire.gpu.global.u32 %0, [%1];" : "=r"(cur) : "l"(f) : "memory");
        if (cur >= target) break;
        if (++spins > 4) __nanosleep(30);
    }
}
__device__ __forceinline__ void signal_flag(unsigned* f) {
    asm volatile("red.release.gpu.global.add.u32 [%0], %1;" :: "l"(f), "r"(1u) : "memory");
}

// ---------------- init: reset flags + copy x0 into state buffer ----------------
__global__ void init_kernel(const float* __restrict__ x0) {
    if (blockIdx.x == 0) {
        d_xf[threadIdx.x] = 0;
        d_gf[threadIdx.x] = 0;
    }
    const int i = blockIdx.x * blockDim.x + threadIdx.x;
    float4 v = *(const float4*)&x0[i * 4];
    *(float4*)&d_xA[i * 4] = v;
}

// ---------------- Phase 1: a{z,f,r} = u @ W + b (FFMA2) ----------------
__global__ void __launch_bounds__(256) inproj_kernel(
    const float* __restrict__ u,
    const float* __restrict__ Wz, const float* __restrict__ Wf, const float* __restrict__ Wr,
    const float* __restrict__ bz, const float* __restrict__ bf, const float* __restrict__ br)
{
    __shared__ float As[BM][BK + 1];
    __shared__ float Bs[BK][BN];

    const int gate = blockIdx.z;
    const float* W    = (gate == 0) ? Wz : (gate == 1) ? Wf : Wr;
    const float* bias = (gate == 0) ? bz : (gate == 1) ? bf : br;
    float* out        = (gate == 0) ? d_az : (gate == 1) ? d_af : d_ar;

    const int m0 = blockIdx.y * BM;
    const int n0 = blockIdx.x * BN;
    const int tid = threadIdx.x;
    const int tx = tid % 16;
    const int ty = tid / 16;

    u64 acc01[4], acc23[4];
#pragma unroll
    for (int i = 0; i < 4; i++) { acc01[i] = 0; acc23[i] = 0; }

    for (int k0 = 0; k0 < NU_; k0 += BK) {
        {
            const int r = tid >> 2, q = tid & 3;
            float4 v = *(const float4*)&u[(size_t)(m0 + r) * NU_ + k0 + q * 4];
            As[r][q * 4 + 0] = v.x; As[r][q * 4 + 1] = v.y;
            As[r][q * 4 + 2] = v.z; As[r][q * 4 + 3] = v.w;
        }
        {
            const int r = tid >> 4, q = tid & 15;
            float4 v = *(const float4*)&W[(size_t)(k0 + r) * NX_ + n0 + q * 4];
            *(float4*)&Bs[r][q * 4] = v;
        }
        __syncthreads();
#pragma unroll
        for (int kk = 0; kk < BK; ++kk) {
            const u64 b01 = *(const u64*)&Bs[kk][tx * 4];
            const u64 b23 = *(const u64*)&Bs[kk][tx * 4 + 2];
#pragma unroll
            for (int i = 0; i < 4; i++) {
                const float av = As[ty * 4 + i][kk];
                const u64 pa = pack2(av, av);
                ffma2(acc01[i], pa, b01);
                ffma2(acc23[i], pa, b23);
            }
        }
        __syncthreads();
    }

    const float b0 = __ldg(&bias[n0 + tx * 4 + 0]);
    const float b1 = __ldg(&bias[n0 + tx * 4 + 1]);
    const float b2 = __ldg(&bias[n0 + tx * 4 + 2]);
    const float b3 = __ldg(&bias[n0 + tx * 4 + 3]);
#pragma unroll
    for (int i = 0; i < 4; i++) {
        float v0, v1, v2, v3;
        unpack2(acc01[i], v0, v1);
        unpack2(acc23[i], v2, v3);
        float4 o = make_float4(v0 + b0, v1 + b1, v2 + b2, v3 + b3);
        *(float4*)&out[(size_t)(m0 + ty * 4 + i) * NX_ + n0 + tx * 4] = o;
    }
}

// ---------------- Phase 2: persistent recurrence (dataflow sync, no grid barriers) ----------------
extern __shared__ float recur_smem[];

__global__ void __launch_bounds__(RTHREADS, 1) recur_kernel(
    const float* __restrict__ Uz, const float* __restrict__ Uf, const float* __restrict__ Ur,
    float* __restrict__ out)
{
    float* Uzf  = recur_smem;                  // [NX_][8 cols][2 gates] = 16384 f
    float* Urs  = Uzf + NX_ * 16;              // [NX_][8] = 8192 f
    float* bufs = Urs + NX_ * 8;               // 6 * 4352 f
    u64*   scr  = (u64*)(bufs + NBUF * BUFF);  // 512 u64 reduction scratch

    const int tid = threadIdx.x;
    const int bid = blockIdx.x;
    const int j0 = bid * CPB;

    const int s     = tid & 127;
    const int khalf = tid >> 7;                // 0: even chunks, 1: odd chunks
    const int row   = s >> 1;
    const int ui    = s & 1;
    const int jb    = j0 + ui * 4;
    const int qown  = bid >> 4;                // own pair-group (cols 128*qown..+127)
    const int poff  = qown;                    // rotated chunk start

    // Stage U slices (one-time). Uzf interleaved {Uz, Uf} per column.
    for (int i = tid; i < NX_ * 8; i += RTHREADS) {
        const int k = i >> 3, col = i & 7;
        Uzf[k * 16 + col * 2 + 0] = __ldg(&Uz[(size_t)k * NX_ + j0 + col]);
        Uzf[k * 16 + col * 2 + 1] = __ldg(&Uf[(size_t)k * NX_ + j0 + col]);
        Urs[i]                    = __ldg(&Ur[(size_t)k * NX_ + j0 + col]);
    }
    __syncthreads();

    const ulonglong2* UzfT = (const ulonglong2*)Uzf + ui * 2;   // + k*4 per k
    const ulonglong2* UrT  = (const ulonglong2*)Urs + ui;       // + k*2 per k

    float zv[4];     // z gate values (khalf==0 threads)
    float4 xc;       // current state for this thread's 4 cols

    for (int t = 0; t < T_; ++t) {
        const float* xsrc = (t & 1) ? d_xB : d_xA;
        float*       xdst = (t & 1) ? d_xA : d_xB;
        float*       gbuf = (t & 1) ? d_gB : d_gA;
        const unsigned xtarget = 16u * (unsigned)t;
        const unsigned gtarget = 16u * (unsigned)(t + 1);

        // ================= ZF phase: z = sig(az + x@Uz), f = sig(af + x@Uf) ============
        u64 acc0 = 0, acc1 = 0, acc2 = 0, acc3 = 0;
        float4 az4, af4;
        if (khalf == 0) {
            az4 = __ldcs((const float4*)&d_az[((size_t)row * T_ + t) * NX_ + jb]);
            af4 = __ldcs((const float4*)&d_af[((size_t)row * T_ + t) * NX_ + jb]);
        }

        {
            const int q0 = poff & 7, q1 = (poff + 1) & 7, q2 = (poff + 2) & 7;
            wait_flag(&d_xf[q0 * 32], xtarget); load_pos(bufs, xsrc, 0, q0, tid);
            wait_flag(&d_xf[q1 * 32], xtarget); load_pos(bufs, xsrc, 1, q1, tid);
            wait_flag(&d_xf[q2 * 32], xtarget); load_pos(bufs, xsrc, 2, q2, tid);
        }
#pragma unroll 1
        for (int p = 0; p < 8; ++p) {
            if (p < 6) cp_wait<2>(); else if (p == 6) cp_wait<1>(); else cp_wait<0>();
            __syncthreads();
            const int pair = (p + poff) & 7;
            const int c = 2 * pair + khalf;
            const float* xb = bufs + ((2 * p + khalf) % NBUF) * BUFF + row * XLD;
            const int k0 = c * KC;
#pragma unroll 8
            for (int kk2 = 0; kk2 < KC / 2; ++kk2) {
                const float2 xp = *(const float2*)(xb + kk2 * 2);
                const u64 p0 = pack2(xp.x, xp.x);
                const u64 p1 = pack2(xp.y, xp.y);
                const int k = k0 + kk2 * 2;
                ulonglong2 A0 = UzfT[(size_t)k * 4];
                ulonglong2 B0 = UzfT[(size_t)k * 4 + 1];
                ffma2(acc0, p0, A0.x); ffma2(acc1, p0, A0.y);
                ffma2(acc2, p0, B0.x); ffma2(acc3, p0, B0.y);
                ulonglong2 A1 = UzfT[(size_t)(k + 1) * 4];
                ulonglong2 B1 = UzfT[(size_t)(k + 1) * 4 + 1];
                ffma2(acc0, p1, A1.x); ffma2(acc1, p1, A1.y);
                ffma2(acc2, p1, B1.x); ffma2(acc3, p1, B1.y);
            }
            __syncthreads();
            if (p < 5) {
                const int np = (p + 3 + poff) & 7;
                wait_flag(&d_xf[np * 32], xtarget);
                load_pos(bufs, xsrc, p + 3, np, tid);
            }
        }
        // cross-half reduction
        if (khalf == 1) {
            ulonglong2* dst = (ulonglong2*)scr;
            dst[s * 2 + 0] = make_ulonglong2(acc0, acc1);
            dst[s * 2 + 1] = make_ulonglong2(acc2, acc3);
        }
        __syncthreads();
        if (khalf == 0) {
            const ulonglong2* src = (const ulonglong2*)scr;
            ulonglong2 o0 = src[s * 2 + 0];
            ulonglong2 o1 = src[s * 2 + 1];
            acc0 = fadd2(acc0, o0.x); acc1 = fadd2(acc1, o0.y);
            acc2 = fadd2(acc2, o1.x); acc3 = fadd2(acc3, o1.y);

            float zp[4], fp[4];
            unpack2(acc0, zp[0], fp[0]); unpack2(acc1, zp[1], fp[1]);
            unpack2(acc2, zp[2], fp[2]); unpack2(acc3, zp[3], fp[3]);
            zp[0] += az4.x; zp[1] += az4.y; zp[2] += az4.z; zp[3] += az4.w;
            fp[0] += af4.x; fp[1] += af4.y; fp[2] += af4.z; fp[3] += af4.w;
            float fv[4];
#pragma unroll
            for (int c2 = 0; c2 < 4; ++c2) {
                zv[c2] = 1.0f / (1.0f + __expf(-zp[c2]));
                fv[c2] = 1.0f / (1.0f + __expf(-fp[c2]));
            }
            xc = __ldcg((const float4*)&xsrc[(size_t)row * NX_ + jb]);
            // io_delay: output at step t is the PRE-update state
            __stcs((float4*)&out[((size_t)row * T_ + t) * NX_ + jb], xc);
            float4 g4;
            g4.x = fv[0] * xc.x; g4.y = fv[1] * xc.y;
            g4.z = fv[2] * xc.z; g4.w = fv[3] * xc.w;
            __stcg((float4*)&gbuf[(size_t)row * NX_ + jb], g4);
        }
        __syncthreads();
        if (tid == 0) signal_flag(&d_gf[qown * 32]);

        // ================= R phase: r = tanh(ar + g@Ur); x_next = z*x + (1-z)*r ========
        u64 racc0 = 0, racc1 = 0;
        float4 ar4;
        if (khalf == 0)
            ar4 = __ldcs((const float4*)&d_ar[((size_t)row * T_ + t) * NX_ + jb]);

        {
            const int q0 = poff & 7, q1 = (poff + 1) & 7, q2 = (poff + 2) & 7;
            wait_flag(&d_gf[q0 * 32], gtarget); load_pos(bufs, gbuf, 0, q0, tid);
            wait_flag(&d_gf[q1 * 32], gtarget); load_pos(bufs, gbuf, 1, q1, tid);
            wait_flag(&d_gf[q2 * 32], gtarget); load_pos(bufs, gbuf, 2, q2, tid);
        }
#pragma unroll 1
        for (int p = 0; p < 8; ++p) {
            if (p < 6) cp_wait<2>(); else if (p == 6) cp_wait<1>(); else cp_wait<0>();
            __syncthreads();
            const int pair = (p + poff) & 7;
            const int c = 2 * pair + khalf;
            const float* gb = bufs + ((2 * p + khalf) % NBUF) * BUFF + row * XLD;
            const int k0 = c * KC;
#pragma unroll 8
            for (int kk2 = 0; kk2 < KC / 2; ++kk2) {
                const float2 gp = *(const float2*)(gb + kk2 * 2);
                const u64 p0 = pack2(gp.x, gp.x);
                const u64 p1 = pack2(gp.y, gp.y);
                const int k = k0 + kk2 * 2;
                ulonglong2 U0 = UrT[(size_t)k * 2];
                ffma2(racc0, p0, U0.x); ffma2(racc1, p0, U0.y);
                ulonglong2 U1 = UrT[(size_t)(k + 1) * 2];
                ffma2(racc0, p1, U1.x); ffma2(racc1, p1, U1.y);
            }
            __syncthreads();
            if (p < 5) {
                const int np = (p + 3 + poff) & 7;
                wait_flag(&d_gf[np * 32], gtarget);
                load_pos(bufs, gbuf, p + 3, np, tid);
            }
        }
        if (khalf == 1)
            ((ulonglong2*)scr)[s] = make_ulonglong2(racc0, racc1);
        __syncthreads();
        if (khalf == 0) {
            ulonglong2 o = ((const ulonglong2*)scr)[s];
            racc0 = fadd2(racc0, o.x); racc1 = fadd2(racc1, o.y);
            float rp[4];
            unpack2(racc0, rp[0], rp[1]); unpack2(racc1, rp[2], rp[3]);
            rp[0] += ar4.x; rp[1] += ar4.y; rp[2] += ar4.z; rp[3] += ar4.w;
            float4 xn;
            xn.x = zv[0] * xc.x + (1.0f - zv[0]) * tanhf(rp[0]);
            xn.y = zv[1] * xc.y + (1.0f - zv[1]) * tanhf(rp[1]);
            xn.z = zv[2] * xc.z + (1.0f - zv[2]) * tanhf(rp[2]);
            xn.w = zv[3] * xc.w + (1.0f - zv[3]) * tanhf(rp[3]);
            __stcg((float4*)&xdst[(size_t)row * NX_ + jb], xn);
        }
        __syncthreads();
        if (tid == 0) signal_flag(&d_xf[qown * 32]);
    }
}

// ---------------- launch ----------------
extern "C" void kernel_launch(void* const* d_in, const int* in_sizes, int n_in,
                              void* d_out, int out_size) {
    const float* u  = (const float*)d_in[0];
    const float* x0 = (const float*)d_in[1];
    const float* Wz = (const float*)d_in[2];
    const float* Uz = (const float*)d_in[3];
    const float* bz = (const float*)d_in[4];
    const float* Wf = (const float*)d_in[5];
    const float* Uf = (const float*)d_in[6];
    const float* bf = (const float*)d_in[7];
    const float* Wr = (const float*)d_in[8];
    const float* Ur = (const float*)d_in[9];
    const float* br = (const float*)d_in[10];
    float* out = (float*)d_out;

    init_kernel<<<64, 256>>>(x0);

    dim3 g1(NX_ / BN, (B_ * T_) / BM, 3);
    inproj_kernel<<<g1, 256>>>(u, Wz, Wf, Wr, bz, bf, br);

    // smem: Uzf 16384 + Ur 8192 + bufs 26112 + scr 1024 floats = 206,848 B
    const int smem_bytes = (NX_ * 16 + NX_ * 8 + NBUF * BUFF + 1024) * (int)sizeof(float);
    cudaFuncSetAttribute(recur_kernel, cudaFuncAttributeMaxDynamicSharedMemorySize, smem_bytes);
    recur_kernel<<<GBLKS, RTHREADS, smem_bytes>>>(Uz, Uf, Ur, out);
}